// round 15
// baseline (speedup 1.0000x reference)
#include <cuda_runtime.h>

// QuantumKernelLayer_65481071403005 — converged R8 recipe + sm_10x
// 256-bit load on the parameter stream (ld.global.v8.f32 fuses the two
// contiguous float4 p-loads into one LDG.256, cutting per-thread LDG
// count 3->2 on the dominant read stream).
//
// Circuit collapsed analytically to 6 cosines/sample:
//   a = x0+p0, b = x1+p1
//   z0 = 0.5*[(1-sin b)*cos(p2-a) + (1+sin b)*cos(p2+a)]
//   z1 = 0.5*[cos(a)*(cos(p3-b)+cos(p3+b)) - (cos(p3-b)-cos(p3+b))]
//
// HBM-streaming bound: 24B read + 8B write per sample, ~18.5us floor.
// Baseline kernel: 19.26-19.68us, DRAM ~73%. Recipe: ILP=2, 512t
// blocks, 30 regs. Rejected by measurement: ILP=1/4, ldcs/stcs,
// persistent+prefetch, 128t, __stwt.

__device__ __forceinline__ float2 qkl_one(float x0, float x1,
                                          float p0, float p1,
                                          float p2, float p3)
{
    float a = x0 + p0;
    float b = x1 + p1;

    float cu = __cosf(p2 - a);
    float cv = __cosf(p2 + a);
    float sb = __sinf(b);
    float ca = __cosf(a);
    float cw = __cosf(p3 - b);
    float ct = __cosf(p3 + b);

    float z0 = 0.5f * ((1.0f - sb) * cu + (1.0f + sb) * cv);
    float z1 = 0.5f * (ca * (cw + ct) - (cw - ct));
    return make_float2(z0, z1);
}

// 256-bit global load (Blackwell sm_100+): 8 consecutive floats.
__device__ __forceinline__ void ldg256(const float* p, float r[8])
{
    asm volatile(
        "ld.global.v8.f32 {%0,%1,%2,%3,%4,%5,%6,%7}, [%8];"
        : "=f"(r[0]), "=f"(r[1]), "=f"(r[2]), "=f"(r[3]),
          "=f"(r[4]), "=f"(r[5]), "=f"(r[6]), "=f"(r[7])
        : "l"(p));
}

__global__ __launch_bounds__(512)
void qkl_kernel2v8(const float4* __restrict__ x2,  // 2 samples per float4
                   const float*  __restrict__ pf,  // parameters, flat
                   float4* __restrict__ o2,        // 2 samples per float4
                   int n)                          // total samples
{
    int i = blockIdx.x * blockDim.x + threadIdx.x;  // group of 2 samples
    int s = i * 2;

    if (s + 2 <= n) {
        // Front-batched: 1x LDG.128 (x) + 1x LDG.256 (p, 2 samples)
        float4 xa = x2[i];
        float pr[8];
        ldg256(pf + 8 * i, pr);

        float2 r0 = qkl_one(xa.x, xa.y, pr[0], pr[1], pr[2], pr[3]);
        float2 r1 = qkl_one(xa.z, xa.w, pr[4], pr[5], pr[6], pr[7]);

        o2[i] = make_float4(r0.x, r0.y, r1.x, r1.y);
    } else if (s < n) {
        // Scalar tail (never taken for B=4194304, kept for safety)
        const float* xf = (const float*)x2;
        float* of = (float*)o2;
        for (int k = s; k < n; k++) {
            float2 r = qkl_one(xf[2 * k], xf[2 * k + 1],
                               pf[4 * k], pf[4 * k + 1],
                               pf[4 * k + 2], pf[4 * k + 3]);
            of[2 * k] = r.x;
            of[2 * k + 1] = r.y;
        }
    }
}

extern "C" void kernel_launch(void* const* d_in, const int* in_sizes, int n_in,
                              void* d_out, int out_size)
{
    const float4* x = (const float4*)d_in[0];   // x: [B,2] float32
    const float*  p = (const float*)d_in[1];    // parameters: [B,4] float32
    float4* out = (float4*)d_out;               // out: [B,2] float32

    int n = in_sizes[0] / 2;                    // B samples
    int threads = 512;
    int groups = (n + 1) / 2;
    int blocks = (groups + threads - 1) / threads;
    qkl_kernel2v8<<<blocks, threads>>>(x, p, out, n);
}

// round 16
// speedup vs baseline: 1.0735x; 1.0735x over previous
#include <cuda_runtime.h>

// QuantumKernelLayer_65481071403005 — FINAL (converged; verified x4).
//
// 2-qubit RY/CX/RY circuit + <Z0>,<Z1> readout, collapsed analytically
// to 6 cosines per sample:
//   a = x0+p0, b = x1+p1
//   z0 = cos(p2)cos(a) - sin(p2)sin(a)sin(b)
//      = 0.5*[(1-sin b)*cos(p2-a) + (1+sin b)*cos(p2+a)]
//   z1 = cos(p3)cos(a)cos(b) - sin(p3)sin(b)
//      = 0.5*[cos(a)*(cos(p3-b)+cos(p3+b)) - (cos(p3-b)-cos(p3+b))]
//
// HBM-streaming bound: 24B read + 8B write per sample (134MB logical),
// ~18.5us floor. Kernel: 19.26/19.36/19.39/19.68us across 4 runs,
// DRAM ~73%, rel_err 2.5e-7 (~96% of floor; remainder is DRAM r/w
// turnaround). L2 write-allocate intentionally kept: dirty output
// lines drain after the kernel window.
//
// Recipe: ILP=2 samples/thread, 3 front-batched LDG.128 + 1 STG.128,
// 512-thread blocks, 30 regs (max resident warps = max chip-wide MLP).
// Measured-and-rejected (each isolated): ILP=1 (22.0us), ILP=4
// (20.8us), ldcs/stcs hints (21.0us), persistent grid + register
// prefetch (20.5us), 128t blocks (19.7us), __stwt (20.7us),
// LDG.256 on p-stream (20.4us — doubles sectors/wavefront in L1tex).

__device__ __forceinline__ float2 qkl_one(float x0, float x1,
                                          float p0, float p1,
                                          float p2, float p3)
{
    float a = x0 + p0;
    float b = x1 + p1;

    float cu = __cosf(p2 - a);
    float cv = __cosf(p2 + a);
    float sb = __sinf(b);
    float ca = __cosf(a);
    float cw = __cosf(p3 - b);
    float ct = __cosf(p3 + b);

    float z0 = 0.5f * ((1.0f - sb) * cu + (1.0f + sb) * cv);
    float z1 = 0.5f * (ca * (cw + ct) - (cw - ct));
    return make_float2(z0, z1);
}

__global__ __launch_bounds__(512)
void qkl_kernel2w(const float4* __restrict__ x2,  // 2 samples per float4
                  const float4* __restrict__ p1v, // 1 sample per float4
                  float4* __restrict__ o2,        // 2 samples per float4
                  int n)                          // total samples
{
    int i = blockIdx.x * blockDim.x + threadIdx.x;  // group of 2 samples
    int s = i * 2;

    if (s + 2 <= n) {
        // Front-batched loads: 3 independent LDG.128
        float4 xa = x2[i];
        float4 pa = p1v[2 * i];
        float4 pb = p1v[2 * i + 1];

        float2 r0 = qkl_one(xa.x, xa.y, pa.x, pa.y, pa.z, pa.w);
        float2 r1 = qkl_one(xa.z, xa.w, pb.x, pb.y, pb.z, pb.w);

        o2[i] = make_float4(r0.x, r0.y, r1.x, r1.y);
    } else if (s < n) {
        // Scalar tail (never taken for B=4194304, kept for safety)
        const float* xf = (const float*)x2;
        const float* pf = (const float*)p1v;
        float* of = (float*)o2;
        for (int k = s; k < n; k++) {
            float2 r = qkl_one(xf[2 * k], xf[2 * k + 1],
                               pf[4 * k], pf[4 * k + 1],
                               pf[4 * k + 2], pf[4 * k + 3]);
            of[2 * k] = r.x;
            of[2 * k + 1] = r.y;
        }
    }
}

extern "C" void kernel_launch(void* const* d_in, const int* in_sizes, int n_in,
                              void* d_out, int out_size)
{
    const float4* x = (const float4*)d_in[0];   // x: [B,2] float32
    const float4* p = (const float4*)d_in[1];   // parameters: [B,4] float32
    float4* out = (float4*)d_out;               // out: [B,2] float32

    int n = in_sizes[0] / 2;                    // B samples
    int threads = 512;
    int groups = (n + 1) / 2;
    int blocks = (groups + threads - 1) / threads;
    qkl_kernel2w<<<blocks, threads>>>(x, p, out, n);
}